// round 14
// baseline (speedup 1.0000x reference)
#include <cuda_runtime.h>
#include <cuda_fp16.h>
#include <cstdint>
#include <math.h>

// ---------------------------------------------------------------------------
// Problem dims
// ---------------------------------------------------------------------------
#define BB 4
#define SS 4096
#define DD 2048
#define EE 2048
#define MM (BB*SS)         // 16384
#define NCHUNK 64
#define LCHUNK (SS/NCHUNK) // 64

// GEMM tiling: CTA covers M=128 x N=64, TWO outputs per CTA (paired weights).
// BK=64, warps 2(m) x 4(n), warp tile 64m x 16n per output.
#define Bb_M 128
#define Bb_N 64
#define Bb_K 64
#define KSTAGES (DD/Bb_K)  // 32

// Stage smem (bytes): A 128 rows x 128B, B 128 rows (64 per weight) x 128B
#define A_OFF 0
#define B_OFF 16384
#define STAGE_BYTES 32768
#define NSTAGE 3
#define SMEM_TOTAL (NSTAGE*STAGE_BYTES)   // 98304 -> 2 CTAs/SM

// ---------------------------------------------------------------------------
// Device scratch
// ---------------------------------------------------------------------------
__device__ __half g_xh[(size_t)MM * DD];          // 64 MB fp16 x
__device__ __half g_wh[(size_t)4 * DD * EE];      // 32 MB fp16 W (q,k,v,g)
__device__ __half g_qg[(size_t)MM * EE];          // 64 MB  q * sigmoid(g)  (fp16)
__device__ __half g_kv[(size_t)MM * EE];          // 64 MB  k * v           (fp16)
__device__ float g_sums[(size_t)BB * EE * NCHUNK];

// ---------------------------------------------------------------------------
// Helpers (sm_80-era instructions only — compile at compute_103 baseline)
// ---------------------------------------------------------------------------
__device__ __forceinline__ uint32_t smem_u32(const void* p) {
    uint32_t a;
    asm("{ .reg .u64 t; cvta.to.shared.u64 t, %1; cvt.u32.u64 %0, t; }"
        : "=r"(a) : "l"(p));
    return a;
}
__device__ __forceinline__ void cp_async16(uint32_t dst, const void* src) {
    asm volatile("cp.async.cg.shared.global [%0], [%1], 16;"
                 :: "r"(dst), "l"(src) : "memory");
}
#define CP_COMMIT() asm volatile("cp.async.commit_group;" ::: "memory")
#define CP_WAIT2()  asm volatile("cp.async.wait_group 2;" ::: "memory")
#define CP_WAIT1()  asm volatile("cp.async.wait_group 1;" ::: "memory")
#define CP_WAIT0()  asm volatile("cp.async.wait_group 0;" ::: "memory")

__device__ __forceinline__ void ldsm4(uint32_t (&r)[4], uint32_t addr) {
    asm volatile("ldmatrix.sync.aligned.m8n8.x4.shared.b16 {%0,%1,%2,%3}, [%4];"
                 : "=r"(r[0]), "=r"(r[1]), "=r"(r[2]), "=r"(r[3]) : "r"(addr));
}
__device__ __forceinline__ void mma16816h(float (&c)[4], const uint32_t (&a)[4],
                                          uint32_t b0, uint32_t b1) {
    asm volatile("mma.sync.aligned.m16n8k16.row.col.f32.f16.f16.f32 "
                 "{%0,%1,%2,%3}, {%4,%5,%6,%7}, {%8,%9}, {%0,%1,%2,%3};"
                 : "+f"(c[0]), "+f"(c[1]), "+f"(c[2]), "+f"(c[3])
                 : "r"(a[0]), "r"(a[1]), "r"(a[2]), "r"(a[3]), "r"(b0), "r"(b1));
}
// SW128 swizzled byte offset inside a [row][128B] tile
__device__ __forceinline__ uint32_t swz(uint32_t row, uint32_t ch) {
    return row * 128u + (((ch ^ (row & 7u)) & 7u) << 4);
}

// ---------------------------------------------------------------------------
// Merged fp32 -> fp16 conversion: grid.y = 12 slices of DD*EE (4M) elements:
//   y in [0,8)  -> x slice y      (x is MM*DD = 32M = 8 slices)
//   y in [8,12) -> Wq,Wk,Wv,Wg    (4M each)
// ---------------------------------------------------------------------------
__global__ __launch_bounds__(256) void conv_all(
    const float* __restrict__ x,
    const float* __restrict__ Wq, const float* __restrict__ Wk,
    const float* __restrict__ Wv, const float* __restrict__ Wg)
{
    const int y = blockIdx.y;
    const float* src;
    __half* dst;
    const size_t base = (size_t)DD * EE;       // elems per slice (4M)
    if (y < 8) { src = x + (size_t)y * base;  dst = g_xh + (size_t)y * base; }
    else {
        const float* W = (y == 8) ? Wq : (y == 9) ? Wk : (y == 10) ? Wv : Wg;
        src = W; dst = g_wh + (size_t)(y - 8) * base;
    }
    size_t i = ((size_t)blockIdx.x * 256 + threadIdx.x) * 8;
    float4 v0 = *(const float4*)(src + i);
    float4 v1 = *(const float4*)(src + i + 4);
    __half2 h[4];
    h[0] = __floats2half2_rn(v0.x, v0.y);
    h[1] = __floats2half2_rn(v0.z, v0.w);
    h[2] = __floats2half2_rn(v1.x, v1.y);
    h[3] = __floats2half2_rn(v1.z, v1.w);
    *(uint4*)(dst + i) = *(uint4*)h;
}

// ---------------------------------------------------------------------------
// Paired fp16 GEMM on mma.sync: ONE CTA computes the same (M,N) tile for TWO
// weight matrices and writes only the elementwise product (as fp16):
//   z=0: qg = (x.Wq^T + bq) * sigmoid(x.Wg^T + bg)
//   z=1: kv = (x.Wk^T + bk) * (x.Wv^T + bv)   + fused per-chunk column sums
// CTA M=128 x N=64 (x2 outputs), BK=64, 3-stage cp.async, warps 2(m) x 4(n).
// Pipeline per kb: sync -> issue loads(kb+2) -> commit -> wait(2) -> SYNC -> mma
// The second sync is REQUIRED: cp.async.wait_group only covers the issuing
// thread's own groups; the post-wait barrier makes all threads' deposits
// visible before any thread's ldmatrix reads the stage.
// ---------------------------------------------------------------------------
__global__ __launch_bounds__(256, 2) void gemm_pair(
    const float* __restrict__ bq, const float* __restrict__ bk,
    const float* __restrict__ bv, const float* __restrict__ bg)
{
    extern __shared__ char smem[];
    const uint32_t sb = smem_u32(smem);
    const int tid = threadIdx.x;
    const int wid = tid >> 5, lane = tid & 31;
    const int wm = wid >> 2, wn = wid & 3;           // warps 2(m) x 4(n)
    const int z = blockIdx.z;
    const size_t m0 = (size_t)blockIdx.y * Bb_M;
    const size_t n0 = (size_t)blockIdx.x * Bb_N;

    // weight indices in g_wh: 0=q, 1=k, 2=v, 3=g
    const int w0i = z ? 1 : 0;
    const int w1i = z ? 2 : 3;
    const float* bias0 = z ? bk : bq;
    const float* bias1 = z ? bv : bg;
    __half* outp = z ? g_kv : g_qg;

    const char* Ag  = (const char*)g_xh + m0 * (DD * 2);
    const char* B0g = (const char*)(g_wh + (size_t)w0i * DD * EE) + n0 * (DD * 2);
    const char* B1g = (const char*)(g_wh + (size_t)w1i * DD * EE) + n0 * (DD * 2);

    const int lrow = tid >> 3;        // 0..31
    const int lch  = tid & 7;         // 0..7

    auto load_stage = [&](int buf, int kb) {
        const uint32_t sbase = sb + buf * STAGE_BYTES;
        const size_t kbyte = (size_t)kb * 128;
        #pragma unroll
        for (int j = 0; j < 4; j++) {          // A: 128 rows
            int row = lrow + j * 32;
            size_t goff = (size_t)row * (DD * 2) + kbyte + lch * 16;
            cp_async16(sbase + A_OFF + swz((uint32_t)row, (uint32_t)lch), Ag + goff);
        }
        #pragma unroll
        for (int j = 0; j < 4; j++) {          // B: rows 0-63 = W0, 64-127 = W1
            int row = lrow + j * 32;
            const char* src = (row < 64)
                ? (B0g + (size_t)row * (DD * 2) + kbyte + lch * 16)
                : (B1g + (size_t)(row - 64) * (DD * 2) + kbyte + lch * 16);
            cp_async16(sbase + B_OFF + swz((uint32_t)row, (uint32_t)lch), src);
        }
    };

    float acc0[4][2][4], acc1[4][2][4];   // [mi][s][frag] for each output
    #pragma unroll
    for (int mi = 0; mi < 4; mi++)
        #pragma unroll
        for (int s = 0; s < 2; s++)
            #pragma unroll
            for (int e = 0; e < 4; e++) { acc0[mi][s][e] = 0.f; acc1[mi][s][e] = 0.f; }

    load_stage(0, 0); CP_COMMIT();
    load_stage(1, 1); CP_COMMIT();

    // ldmatrix lane->addr mapping
    const uint32_t arow = (uint32_t)(wm * 64) + (uint32_t)(lane & 15); // + mi*16
    const uint32_t ahib = (uint32_t)(lane >> 4);
    const uint32_t brow = (uint32_t)(wn * 16) + (uint32_t)(lane & 7) +
                          (uint32_t)((lane & 16) >> 1);                // 16-row group
    const uint32_t bhib = (uint32_t)((lane >> 3) & 1);

    for (int kb = 0; kb < KSTAGES; kb++) {
        __syncthreads();                       // all warps done reading stage kb-1
        if (kb + 2 < KSTAGES) {
            load_stage((kb + 2) % NSTAGE, kb + 2);   // (kb+2)%3 == (kb-1)%3, free
            CP_COMMIT();
            CP_WAIT2();                        // drain own group kb
        } else if (kb + 1 < KSTAGES) {
            CP_WAIT1();
        } else {
            CP_WAIT0();
        }
        __syncthreads();                       // ALL threads' group-kb deposits visible

        const uint32_t sbase = sb + (kb % NSTAGE) * STAGE_BYTES;
        #pragma unroll
        for (int kk = 0; kk < 4; kk++) {
            uint32_t af[4][4];
            #pragma unroll
            for (int mi = 0; mi < 4; mi++) {
                uint32_t off = swz(arow + mi * 16, kk * 2 + ahib);
                ldsm4(af[mi], sbase + A_OFF + off);
            }
            uint32_t b0f[4], b1f[4];
            {
                uint32_t off0 = swz(brow, kk * 2 + bhib);
                uint32_t off1 = swz(brow + 64, kk * 2 + bhib);
                ldsm4(b0f, sbase + B_OFF + off0);
                ldsm4(b1f, sbase + B_OFF + off1);
            }
            #pragma unroll
            for (int mi = 0; mi < 4; mi++) {
                #pragma unroll
                for (int s = 0; s < 2; s++) {
                    mma16816h(acc0[mi][s], af[mi], b0f[s*2], b0f[s*2+1]);
                    mma16816h(acc1[mi][s], af[mi], b1f[s*2], b1f[s*2+1]);
                }
            }
        }
    }

    // Epilogue: p = acc0 + bias0 ; r = acc1 + bias1 (sigmoid for z==0);
    // write p*r as half2; for z==1 also accumulate per-chunk column sums (fp32).
    const int crow = lane >> 2;          // 0..7
    const int ccol = (lane & 3) * 2;     // 0,2,4,6
    float colsum[2][2] = {{0.f, 0.f}, {0.f, 0.f}};
    #pragma unroll
    for (int s = 0; s < 2; s++) {
        size_t n = n0 + wn * 16 + s * 8 + ccol;
        float p0b = __ldg(bias0 + n), p1b = __ldg(bias0 + n + 1);
        float r0b = __ldg(bias1 + n), r1b = __ldg(bias1 + n + 1);
        #pragma unroll
        for (int mi = 0; mi < 4; mi++) {
            size_t m = m0 + wm * 64 + mi * 16 + crow;
            float pA0 = acc0[mi][s][0] + p0b, pA1 = acc0[mi][s][1] + p1b;
            float pB0 = acc0[mi][s][2] + p0b, pB1 = acc0[mi][s][3] + p1b;
            float rA0 = acc1[mi][s][0] + r0b, rA1 = acc1[mi][s][1] + r1b;
            float rB0 = acc1[mi][s][2] + r0b, rB1 = acc1[mi][s][3] + r1b;
            if (z == 0) {
                rA0 = 1.f/(1.f+expf(-rA0)); rA1 = 1.f/(1.f+expf(-rA1));
                rB0 = 1.f/(1.f+expf(-rB0)); rB1 = 1.f/(1.f+expf(-rB1));
            }
            float kvA0 = pA0 * rA0, kvA1 = pA1 * rA1;
            float kvB0 = pB0 * rB0, kvB1 = pB1 * rB1;
            if (z == 1) {
                colsum[s][0] += kvA0 + kvB0;
                colsum[s][1] += kvA1 + kvB1;
            }
            *(__half2*)(outp + m * (size_t)EE + n) = __floats2half2_rn(kvA0, kvA1);
            *(__half2*)(outp + (m + 8) * (size_t)EE + n) = __floats2half2_rn(kvB0, kvB1);
        }
    }

    if (z == 1) {
        // reduce colsum over the 8 crow groups (lanes sharing lane&3)
        #pragma unroll
        for (int s = 0; s < 2; s++) {
            #pragma unroll
            for (int j = 0; j < 2; j++) {
                float v = colsum[s][j];
                v += __shfl_xor_sync(0xffffffffu, v, 4);
                v += __shfl_xor_sync(0xffffffffu, v, 8);
                v += __shfl_xor_sync(0xffffffffu, v, 16);
                colsum[s][j] = v;
            }
        }
        if (lane < 4) {
            const int b = (int)(m0 >> 12);                 // m0 / 4096
            const int c = (int)((m0 & 4095) >> 6) + wm;    // chunk in batch
            #pragma unroll
            for (int s = 0; s < 2; s++) {
                size_t e = n0 + wn * 16 + s * 8 + lane * 2;
                g_sums[((size_t)b * EE + e)     * NCHUNK + c] = colsum[s][0];
                g_sums[((size_t)b * EE + e + 1) * NCHUNK + c] = colsum[s][1];
            }
        }
    }
}

// ---------------------------------------------------------------------------
// Exclusive scan of chunk sums (in place): one warp per chain of 64,
// float2 per lane, shfl inclusive scan -> coalesced.
// ---------------------------------------------------------------------------
__global__ __launch_bounds__(256) void scan_sums()
{
    const int wid = threadIdx.x >> 5, lane = threadIdx.x & 31;
    const size_t chain = (size_t)blockIdx.x * 8 + wid;     // 0..8191
    float* p = g_sums + chain * NCHUNK;
    float2 vv = *(float2*)(p + lane * 2);
    float pairsum = vv.x + vv.y;
    float inc = pairsum;
    #pragma unroll
    for (int d = 1; d < 32; d <<= 1) {
        float t = __shfl_up_sync(0xffffffffu, inc, d);
        if (lane >= d) inc += t;
    }
    float excl = inc - pairsum;
    *(float2*)(p + lane * 2) = make_float2(excl, excl + vv.x);
}

// ---------------------------------------------------------------------------
// Finalize: local inclusive scan + qg * state.  Two columns per thread
// (half2 loads of qg/kv, float2 stores of out).
// ---------------------------------------------------------------------------
__global__ __launch_bounds__(256) void finalize(float* __restrict__ out)
{
    const int e2 = blockIdx.x * 256 + threadIdx.x;   // column pair id, 0..1023
    const int e = e2 * 2;
    const int c = blockIdx.y;
    const int b = blockIdx.z;
    float run0 = g_sums[((size_t)b * EE + e)     * NCHUNK + c];
    float run1 = g_sums[((size_t)b * EE + e + 1) * NCHUNK + c];
    size_t idx = ((size_t)(b * SS + c * LCHUNK)) * EE + e;
    #pragma unroll 4
    for (int i = 0; i < LCHUNK; i++) {
        float2 kv = __half22float2(*(const __half2*)(g_kv + idx));
        float2 qg = __half22float2(*(const __half2*)(g_qg + idx));
        run0 += kv.x;
        run1 += kv.y;
        *(float2*)(out + idx) = make_float2(qg.x * run0, qg.y * run1);
        idx += EE;
    }
}

// ---------------------------------------------------------------------------
// Launch
// ---------------------------------------------------------------------------
extern "C" void kernel_launch(void* const* d_in, const int* in_sizes, int n_in,
                              void* d_out, int out_size)
{
    const float* x  = (const float*)d_in[0];
    const float* Wq = (const float*)d_in[1];
    const float* bq = (const float*)d_in[2];
    const float* Wk = (const float*)d_in[3];
    const float* bk = (const float*)d_in[4];
    const float* Wv = (const float*)d_in[5];
    const float* bv = (const float*)d_in[6];
    const float* Wg = (const float*)d_in[7];
    const float* bg = (const float*)d_in[8];
    float* out = (float*)d_out;

    cudaFuncSetAttribute(gemm_pair,
        cudaFuncAttributeMaxDynamicSharedMemorySize, SMEM_TOTAL);

    // one launch converts x (8 slices) + all four W (4 slices)
    conv_all<<<dim3(((size_t)DD * EE / 8) / 256, 12), 256>>>(x, Wq, Wk, Wv, Wg);

    gemm_pair<<<dim3(EE/Bb_N, MM/Bb_M, 2), 256, SMEM_TOTAL>>>(bq, bk, bv, bg);

    scan_sums<<<(BB * EE) / 8, 256>>>();

    dim3 gridF(EE / 512, NCHUNK, BB);
    finalize<<<gridF, 256>>>(out);
}

// round 15
// speedup vs baseline: 1.0068x; 1.0068x over previous
#include <cuda_runtime.h>
#include <cuda_fp16.h>
#include <cstdint>
#include <math.h>

// ---------------------------------------------------------------------------
// Problem dims
// ---------------------------------------------------------------------------
#define BB 4
#define SS 4096
#define DD 2048
#define EE 2048
#define MM (BB*SS)         // 16384
#define NCHUNK 64
#define LCHUNK (SS/NCHUNK) // 64

// GEMM tiling: CTA covers M=128 x N=64, TWO outputs per CTA (paired weights).
// BK=64, warps 2(m) x 4(n), warp tile 64m x 16n per output.
#define Bb_M 128
#define Bb_N 64
#define Bb_K 64
#define KSTAGES (DD/Bb_K)  // 32

// Stage smem (bytes): A 128 rows x 128B, B 128 rows (64 per weight) x 128B
#define A_OFF 0
#define B_OFF 16384
#define STAGE_BYTES 32768
#define NSTAGE 3
#define SMEM_TOTAL (NSTAGE*STAGE_BYTES)   // 98304 -> 2 CTAs/SM

// ---------------------------------------------------------------------------
// Device scratch
// ---------------------------------------------------------------------------
__device__ __half g_xh[(size_t)MM * DD];          // 64 MB fp16 x
__device__ __half g_wh[(size_t)4 * DD * EE];      // 32 MB fp16 W (q,k,v,g)
__device__ __half g_qg[(size_t)MM * EE];          // 64 MB  q * sigmoid(g)  (fp16)
__device__ __half g_kv[(size_t)MM * EE];          // 64 MB  k * v           (fp16)
__device__ float g_sums[(size_t)BB * EE * NCHUNK];

// ---------------------------------------------------------------------------
// Helpers (sm_80-era instructions only — compile at compute_103 baseline)
// ---------------------------------------------------------------------------
__device__ __forceinline__ uint32_t smem_u32(const void* p) {
    uint32_t a;
    asm("{ .reg .u64 t; cvta.to.shared.u64 t, %1; cvt.u32.u64 %0, t; }"
        : "=r"(a) : "l"(p));
    return a;
}
__device__ __forceinline__ void cp_async16(uint32_t dst, const void* src) {
    asm volatile("cp.async.cg.shared.global [%0], [%1], 16;"
                 :: "r"(dst), "l"(src) : "memory");
}
#define CP_COMMIT() asm volatile("cp.async.commit_group;" ::: "memory")
#define CP_WAIT1()  asm volatile("cp.async.wait_group 1;" ::: "memory")
#define CP_WAIT0()  asm volatile("cp.async.wait_group 0;" ::: "memory")

__device__ __forceinline__ void ldsm4(uint32_t (&r)[4], uint32_t addr) {
    asm volatile("ldmatrix.sync.aligned.m8n8.x4.shared.b16 {%0,%1,%2,%3}, [%4];"
                 : "=r"(r[0]), "=r"(r[1]), "=r"(r[2]), "=r"(r[3]) : "r"(addr));
}
__device__ __forceinline__ void mma16816h(float (&c)[4], const uint32_t (&a)[4],
                                          uint32_t b0, uint32_t b1) {
    asm volatile("mma.sync.aligned.m16n8k16.row.col.f32.f16.f16.f32 "
                 "{%0,%1,%2,%3}, {%4,%5,%6,%7}, {%8,%9}, {%0,%1,%2,%3};"
                 : "+f"(c[0]), "+f"(c[1]), "+f"(c[2]), "+f"(c[3])
                 : "r"(a[0]), "r"(a[1]), "r"(a[2]), "r"(a[3]), "r"(b0), "r"(b1));
}
// SW128 swizzled byte offset inside a [row][128B] tile
__device__ __forceinline__ uint32_t swz(uint32_t row, uint32_t ch) {
    return row * 128u + (((ch ^ (row & 7u)) & 7u) << 4);
}

// ---------------------------------------------------------------------------
// Merged fp32 -> fp16 conversion: grid.y = 12 slices of DD*EE (4M) elements:
//   y in [0,8)  -> x slice y      (x is MM*DD = 32M = 8 slices)
//   y in [8,12) -> Wq,Wk,Wv,Wg    (4M each)
// ---------------------------------------------------------------------------
__global__ __launch_bounds__(256) void conv_all(
    const float* __restrict__ x,
    const float* __restrict__ Wq, const float* __restrict__ Wk,
    const float* __restrict__ Wv, const float* __restrict__ Wg)
{
    const int y = blockIdx.y;
    const float* src;
    __half* dst;
    const size_t base = (size_t)DD * EE;       // elems per slice (4M)
    if (y < 8) { src = x + (size_t)y * base;  dst = g_xh + (size_t)y * base; }
    else {
        const float* W = (y == 8) ? Wq : (y == 9) ? Wk : (y == 10) ? Wv : Wg;
        src = W; dst = g_wh + (size_t)(y - 8) * base;
    }
    size_t i = ((size_t)blockIdx.x * 256 + threadIdx.x) * 8;
    float4 v0 = *(const float4*)(src + i);
    float4 v1 = *(const float4*)(src + i + 4);
    __half2 h[4];
    h[0] = __floats2half2_rn(v0.x, v0.y);
    h[1] = __floats2half2_rn(v0.z, v0.w);
    h[2] = __floats2half2_rn(v1.x, v1.y);
    h[3] = __floats2half2_rn(v1.z, v1.w);
    *(uint4*)(dst + i) = *(uint4*)h;
}

// ---------------------------------------------------------------------------
// Paired fp16 GEMM on mma.sync: ONE CTA computes the same (M,N) tile for TWO
// weight matrices and writes only the elementwise product (as fp16):
//   z=0: qg = (x.Wq^T + bq) * sigmoid(x.Wg^T + bg)
//   z=1: kv = (x.Wk^T + bk) * (x.Wv^T + bv)   + fused per-chunk column sums
// CTA M=128 x N=64 (x2 outputs), BK=64, 3-stage cp.async, warps 2(m) x 4(n).
// Pipeline per kb (proven R11 order): wait -> sync -> issue loads(kb+2) -> mma.
// The sync AFTER the wait is what makes all threads' cp.async deposits for
// stage kb visible before any thread's ldmatrix reads them.
// ---------------------------------------------------------------------------
__global__ __launch_bounds__(256, 2) void gemm_pair(
    const float* __restrict__ bq, const float* __restrict__ bk,
    const float* __restrict__ bv, const float* __restrict__ bg)
{
    extern __shared__ char smem[];
    const uint32_t sb = smem_u32(smem);
    const int tid = threadIdx.x;
    const int wid = tid >> 5, lane = tid & 31;
    const int wm = wid >> 2, wn = wid & 3;           // warps 2(m) x 4(n)
    const int z = blockIdx.z;
    const size_t m0 = (size_t)blockIdx.y * Bb_M;
    const size_t n0 = (size_t)blockIdx.x * Bb_N;

    // weight indices in g_wh: 0=q, 1=k, 2=v, 3=g
    const int w0i = z ? 1 : 0;
    const int w1i = z ? 2 : 3;
    const float* bias0 = z ? bk : bq;
    const float* bias1 = z ? bv : bg;
    __half* outp = z ? g_kv : g_qg;

    const char* Ag  = (const char*)g_xh + m0 * (DD * 2);
    const char* B0g = (const char*)(g_wh + (size_t)w0i * DD * EE) + n0 * (DD * 2);
    const char* B1g = (const char*)(g_wh + (size_t)w1i * DD * EE) + n0 * (DD * 2);

    const int lrow = tid >> 3;        // 0..31
    const int lch  = tid & 7;         // 0..7

    auto load_stage = [&](int buf, int kb) {
        const uint32_t sbase = sb + buf * STAGE_BYTES;
        const size_t kbyte = (size_t)kb * 128;
        #pragma unroll
        for (int j = 0; j < 4; j++) {          // A: 128 rows
            int row = lrow + j * 32;
            size_t goff = (size_t)row * (DD * 2) + kbyte + lch * 16;
            cp_async16(sbase + A_OFF + swz((uint32_t)row, (uint32_t)lch), Ag + goff);
        }
        #pragma unroll
        for (int j = 0; j < 4; j++) {          // B: rows 0-63 = W0, 64-127 = W1
            int row = lrow + j * 32;
            const char* src = (row < 64)
                ? (B0g + (size_t)row * (DD * 2) + kbyte + lch * 16)
                : (B1g + (size_t)(row - 64) * (DD * 2) + kbyte + lch * 16);
            cp_async16(sbase + B_OFF + swz((uint32_t)row, (uint32_t)lch), src);
        }
    };

    float acc0[4][2][4], acc1[4][2][4];   // [mi][s][frag] for each output
    #pragma unroll
    for (int mi = 0; mi < 4; mi++)
        #pragma unroll
        for (int s = 0; s < 2; s++)
            #pragma unroll
            for (int e = 0; e < 4; e++) { acc0[mi][s][e] = 0.f; acc1[mi][s][e] = 0.f; }

    load_stage(0, 0); CP_COMMIT();
    load_stage(1, 1); CP_COMMIT();

    // ldmatrix lane->addr mapping
    const uint32_t arow = (uint32_t)(wm * 64) + (uint32_t)(lane & 15); // + mi*16
    const uint32_t ahib = (uint32_t)(lane >> 4);
    const uint32_t brow = (uint32_t)(wn * 16) + (uint32_t)(lane & 7) +
                          (uint32_t)((lane & 16) >> 1);                // 16-row group
    const uint32_t bhib = (uint32_t)((lane >> 3) & 1);

    for (int kb = 0; kb < KSTAGES; kb++) {
        if (kb + 1 < KSTAGES) { CP_WAIT1(); } else { CP_WAIT0(); }
        __syncthreads();
        if (kb + 2 < KSTAGES) { load_stage((kb + 2) % NSTAGE, kb + 2); CP_COMMIT(); }

        const uint32_t sbase = sb + (kb % NSTAGE) * STAGE_BYTES;
        #pragma unroll
        for (int kk = 0; kk < 4; kk++) {
            uint32_t af[4][4];
            #pragma unroll
            for (int mi = 0; mi < 4; mi++) {
                uint32_t off = swz(arow + mi * 16, kk * 2 + ahib);
                ldsm4(af[mi], sbase + A_OFF + off);
            }
            uint32_t b0f[4], b1f[4];
            {
                uint32_t off0 = swz(brow, kk * 2 + bhib);
                uint32_t off1 = swz(brow + 64, kk * 2 + bhib);
                ldsm4(b0f, sbase + B_OFF + off0);
                ldsm4(b1f, sbase + B_OFF + off1);
            }
            #pragma unroll
            for (int mi = 0; mi < 4; mi++) {
                #pragma unroll
                for (int s = 0; s < 2; s++) {
                    mma16816h(acc0[mi][s], af[mi], b0f[s*2], b0f[s*2+1]);
                    mma16816h(acc1[mi][s], af[mi], b1f[s*2], b1f[s*2+1]);
                }
            }
        }
    }

    // Epilogue: p = acc0 + bias0 ; r = acc1 + bias1 (sigmoid for z==0);
    // write p*r as half2; for z==1 also accumulate per-chunk column sums (fp32).
    const int crow = lane >> 2;          // 0..7
    const int ccol = (lane & 3) * 2;     // 0,2,4,6
    float colsum[2][2] = {{0.f, 0.f}, {0.f, 0.f}};
    #pragma unroll
    for (int s = 0; s < 2; s++) {
        size_t n = n0 + wn * 16 + s * 8 + ccol;
        float p0b = __ldg(bias0 + n), p1b = __ldg(bias0 + n + 1);
        float r0b = __ldg(bias1 + n), r1b = __ldg(bias1 + n + 1);
        #pragma unroll
        for (int mi = 0; mi < 4; mi++) {
            size_t m = m0 + wm * 64 + mi * 16 + crow;
            float pA0 = acc0[mi][s][0] + p0b, pA1 = acc0[mi][s][1] + p1b;
            float pB0 = acc0[mi][s][2] + p0b, pB1 = acc0[mi][s][3] + p1b;
            float rA0 = acc1[mi][s][0] + r0b, rA1 = acc1[mi][s][1] + r1b;
            float rB0 = acc1[mi][s][2] + r0b, rB1 = acc1[mi][s][3] + r1b;
            if (z == 0) {
                rA0 = 1.f/(1.f+expf(-rA0)); rA1 = 1.f/(1.f+expf(-rA1));
                rB0 = 1.f/(1.f+expf(-rB0)); rB1 = 1.f/(1.f+expf(-rB1));
            }
            float kvA0 = pA0 * rA0, kvA1 = pA1 * rA1;
            float kvB0 = pB0 * rB0, kvB1 = pB1 * rB1;
            if (z == 1) {
                colsum[s][0] += kvA0 + kvB0;
                colsum[s][1] += kvA1 + kvB1;
            }
            *(__half2*)(outp + m * (size_t)EE + n) = __floats2half2_rn(kvA0, kvA1);
            *(__half2*)(outp + (m + 8) * (size_t)EE + n) = __floats2half2_rn(kvB0, kvB1);
        }
    }

    if (z == 1) {
        // reduce colsum over the 8 crow groups (lanes sharing lane&3)
        #pragma unroll
        for (int s = 0; s < 2; s++) {
            #pragma unroll
            for (int j = 0; j < 2; j++) {
                float v = colsum[s][j];
                v += __shfl_xor_sync(0xffffffffu, v, 4);
                v += __shfl_xor_sync(0xffffffffu, v, 8);
                v += __shfl_xor_sync(0xffffffffu, v, 16);
                colsum[s][j] = v;
            }
        }
        if (lane < 4) {
            const int b = (int)(m0 >> 12);                 // m0 / 4096
            const int c = (int)((m0 & 4095) >> 6) + wm;    // chunk in batch
            #pragma unroll
            for (int s = 0; s < 2; s++) {
                size_t e = n0 + wn * 16 + s * 8 + lane * 2;
                g_sums[((size_t)b * EE + e)     * NCHUNK + c] = colsum[s][0];
                g_sums[((size_t)b * EE + e + 1) * NCHUNK + c] = colsum[s][1];
            }
        }
    }
}

// ---------------------------------------------------------------------------
// Exclusive scan of chunk sums (in place): one warp per chain of 64,
// float2 per lane, shfl inclusive scan -> coalesced.
// ---------------------------------------------------------------------------
__global__ __launch_bounds__(256) void scan_sums()
{
    const int wid = threadIdx.x >> 5, lane = threadIdx.x & 31;
    const size_t chain = (size_t)blockIdx.x * 8 + wid;     // 0..8191
    float* p = g_sums + chain * NCHUNK;
    float2 vv = *(float2*)(p + lane * 2);
    float pairsum = vv.x + vv.y;
    float inc = pairsum;
    #pragma unroll
    for (int d = 1; d < 32; d <<= 1) {
        float t = __shfl_up_sync(0xffffffffu, inc, d);
        if (lane >= d) inc += t;
    }
    float excl = inc - pairsum;
    *(float2*)(p + lane * 2) = make_float2(excl, excl + vv.x);
}

// ---------------------------------------------------------------------------
// Finalize: local inclusive scan + qg * state.  FOUR columns per thread
// (uint2 loads of qg/kv = 4 halves, float4 stores of out).
// ---------------------------------------------------------------------------
__global__ __launch_bounds__(256) void finalize(float* __restrict__ out)
{
    const int e4 = blockIdx.x * 256 + threadIdx.x;   // column quad id, 0..511
    const int e = e4 * 4;
    const int c = blockIdx.y;
    const int b = blockIdx.z;
    float run0 = g_sums[((size_t)b * EE + e)     * NCHUNK + c];
    float run1 = g_sums[((size_t)b * EE + e + 1) * NCHUNK + c];
    float run2 = g_sums[((size_t)b * EE + e + 2) * NCHUNK + c];
    float run3 = g_sums[((size_t)b * EE + e + 3) * NCHUNK + c];
    size_t idx = ((size_t)(b * SS + c * LCHUNK)) * EE + e;
    #pragma unroll 4
    for (int i = 0; i < LCHUNK; i++) {
        uint2 kvr = *(const uint2*)(g_kv + idx);
        uint2 qgr = *(const uint2*)(g_qg + idx);
        float2 kv0 = __half22float2(*(__half2*)&kvr.x);
        float2 kv1 = __half22float2(*(__half2*)&kvr.y);
        float2 qg0 = __half22float2(*(__half2*)&qgr.x);
        float2 qg1 = __half22float2(*(__half2*)&qgr.y);
        run0 += kv0.x; run1 += kv0.y; run2 += kv1.x; run3 += kv1.y;
        float4 o;
        o.x = qg0.x * run0; o.y = qg0.y * run1;
        o.z = qg1.x * run2; o.w = qg1.y * run3;
        *(float4*)(out + idx) = o;
        idx += EE;
    }
}

// ---------------------------------------------------------------------------
// Launch
// ---------------------------------------------------------------------------
extern "C" void kernel_launch(void* const* d_in, const int* in_sizes, int n_in,
                              void* d_out, int out_size)
{
    const float* x  = (const float*)d_in[0];
    const float* Wq = (const float*)d_in[1];
    const float* bq = (const float*)d_in[2];
    const float* Wk = (const float*)d_in[3];
    const float* bk = (const float*)d_in[4];
    const float* Wv = (const float*)d_in[5];
    const float* bv = (const float*)d_in[6];
    const float* Wg = (const float*)d_in[7];
    const float* bg = (const float*)d_in[8];
    float* out = (float*)d_out;

    cudaFuncSetAttribute(gemm_pair,
        cudaFuncAttributeMaxDynamicSharedMemorySize, SMEM_TOTAL);

    // one launch converts x (8 slices) + all four W (4 slices)
    conv_all<<<dim3(((size_t)DD * EE / 8) / 256, 12), 256>>>(x, Wq, Wk, Wv, Wg);

    gemm_pair<<<dim3(EE/Bb_N, MM/Bb_M, 2), 256, SMEM_TOTAL>>>(bq, bk, bv, bg);

    scan_sums<<<(BB * EE) / 8, 256>>>();

    dim3 gridF(EE / 1024, NCHUNK, BB);
    finalize<<<gridF, 256>>>(out);
}